// round 2
// baseline (speedup 1.0000x reference)
#include <cuda_runtime.h>
#include <cstdint>

#define NN 100000
#define EE 1600000
#define FIN 128
#define HID 64
#define NG 512
#define BN_EPS_F 1e-5f

// Scratch (allocation-free rule: __device__ globals).
__device__ __align__(16) float g_Y[(size_t)NN * HID];   // projected row used for gather
__device__ __align__(16) float g_A[(size_t)NN * HID];   // self + bias accumulator (scatter target)

__device__ __forceinline__ void red_add_v4(float* p, float a, float b, float c, float d) {
    asm volatile("red.global.add.v4.f32 [%0], {%1,%2,%3,%4};"
                 :: "l"(p), "f"(a), "f"(b), "f"(c), "f"(d) : "memory");
}

// ---------------------------------------------------------------- zero output
__global__ void k_zero(float* __restrict__ out, int n) {
    int i = blockIdx.x * blockDim.x + threadIdx.x;
    if (i < n) out[i] = 0.f;
}

// ------------------------------------------------- K1: Y = x @ W1a^T ; A = Y + b1a
// 2 nodes x 32 outputs per thread: W float4 feeds 8 FMAs, two independent acc chains.
__global__ __launch_bounds__(128) void k_in_proj(
    const float* __restrict__ x, const float* __restrict__ W, const float* __restrict__ b)
{
    __shared__ float Wt[FIN * HID];   // Wt[k*64+f] = W[f][k]
    __shared__ float bs[HID];
    for (int i = threadIdx.x; i < FIN * HID; i += 128) {
        int k = i >> 6, f = i & 63;
        Wt[k * HID + f] = W[f * FIN + k];
    }
    if (threadIdx.x < HID) bs[threadIdx.x] = b[threadIdx.x];
    __syncthreads();

    int p = threadIdx.x >> 1, h = threadIdx.x & 1;
    int nA = blockIdx.x * 128 + 2 * p;
    int nB = nA + 1;
    bool vA = nA < NN, vB = nB < NN;

    const float4* xA = (const float4*)(x + (size_t)nA * FIN);
    const float4* xB = (const float4*)(x + (size_t)nB * FIN);

    float accA[32], accB[32];
#pragma unroll
    for (int j = 0; j < 32; j++) { accA[j] = 0.f; accB[j] = 0.f; }

    for (int k4 = 0; k4 < FIN / 4; k4++) {
        float4 a4 = vA ? xA[k4] : make_float4(0.f, 0.f, 0.f, 0.f);
        float4 b4 = vB ? xB[k4] : make_float4(0.f, 0.f, 0.f, 0.f);
#pragma unroll
        for (int s = 0; s < 4; s++) {
            float xa = (s == 0) ? a4.x : (s == 1) ? a4.y : (s == 2) ? a4.z : a4.w;
            float xb = (s == 0) ? b4.x : (s == 1) ? b4.y : (s == 2) ? b4.z : b4.w;
            const float4* wr = (const float4*)(Wt + (4 * k4 + s) * HID + 32 * h);
#pragma unroll
            for (int f4 = 0; f4 < 8; f4++) {
                float4 w = wr[f4];
                accA[4*f4+0] = fmaf(xa, w.x, accA[4*f4+0]);
                accA[4*f4+1] = fmaf(xa, w.y, accA[4*f4+1]);
                accA[4*f4+2] = fmaf(xa, w.z, accA[4*f4+2]);
                accA[4*f4+3] = fmaf(xa, w.w, accA[4*f4+3]);
                accB[4*f4+0] = fmaf(xb, w.x, accB[4*f4+0]);
                accB[4*f4+1] = fmaf(xb, w.y, accB[4*f4+1]);
                accB[4*f4+2] = fmaf(xb, w.z, accB[4*f4+2]);
                accB[4*f4+3] = fmaf(xb, w.w, accB[4*f4+3]);
            }
        }
    }

    if (vA) {
        float4* Yo = (float4*)(g_Y + (size_t)nA * HID + 32 * h);
        float4* Ao = (float4*)(g_A + (size_t)nA * HID + 32 * h);
#pragma unroll
        for (int f4 = 0; f4 < 8; f4++) {
            float4 v = make_float4(accA[4*f4], accA[4*f4+1], accA[4*f4+2], accA[4*f4+3]);
            Yo[f4] = v;
            int fb = 32 * h + 4 * f4;
            Ao[f4] = make_float4(v.x + bs[fb], v.y + bs[fb+1], v.z + bs[fb+2], v.w + bs[fb+3]);
        }
    }
    if (vB) {
        float4* Yo = (float4*)(g_Y + (size_t)nB * HID + 32 * h);
        float4* Ao = (float4*)(g_A + (size_t)nB * HID + 32 * h);
#pragma unroll
        for (int f4 = 0; f4 < 8; f4++) {
            float4 v = make_float4(accB[4*f4], accB[4*f4+1], accB[4*f4+2], accB[4*f4+3]);
            Yo[f4] = v;
            int fb = 32 * h + 4 * f4;
            Ao[f4] = make_float4(v.x + bs[fb], v.y + bs[fb+1], v.z + bs[fb+2], v.w + bs[fb+3]);
        }
    }
}

// ------------------------------------------------- scatter: A[dst] += Y[src]
// 16 threads per edge, one float4 each, vector RED. Y/A are L2-resident.
__global__ __launch_bounds__(256) void k_scatter(const int* __restrict__ ei)
{
    int t = blockIdx.x * 256 + threadIdx.x;      // < 25.6M, fits int32
    int e = t >> 4;
    int part = t & 15;
    if (e >= EE) return;
    int s = ei[e];        // src row
    int d = ei[EE + e];   // dst row
    float4 v = ((const float4*)g_Y)[(size_t)s * 16 + part];
    red_add_v4(g_A + (size_t)d * HID + part * 4, v.x, v.y, v.z, v.w);
}

// ------------------------------------------------- k_mid: fused
//   H1 = relu(bn1(relu(A1) @ W1b^T + b1b))      (H1 staged in SMEM, transposed)
//   Y2 = H1 @ W2a^T  -> g_Y ;  A2 = Y2 + b2a -> g_A
// Block = 128 threads = 128 nodes; thread = (pair, half): 2 nodes x 32 outputs.
#define HS_W 130   // padded transposed H tile row width (conflict-free phase-2 reads)

__global__ __launch_bounds__(128) void k_mid(
    const float* __restrict__ W1b, const float* __restrict__ b1b,
    const float* __restrict__ g1,  const float* __restrict__ be1,
    const float* __restrict__ m1,  const float* __restrict__ v1,
    const float* __restrict__ W2a, const float* __restrict__ b2a)
{
    extern __shared__ float sm[];
    float* Wt  = sm;                        // 64*64
    float* Hs  = Wt + HID * HID;            // 64*HS_W, Hs[f*HS_W + localNode]
    float* sc  = Hs + HID * HS_W;
    float* sh  = sc + HID;
    float* bs2 = sh + HID;

    int tid = threadIdx.x;
    for (int i = tid; i < HID * HID; i += 128) {
        int k = i >> 6, f = i & 63;
        Wt[k * HID + f] = W1b[f * HID + k];
    }
    if (tid < HID) {
        float s = g1[tid] * rsqrtf(v1[tid] + BN_EPS_F);
        sc[tid] = s;
        sh[tid] = (b1b[tid] - m1[tid]) * s + be1[tid];
        bs2[tid] = b2a[tid];
    }
    __syncthreads();

    int p = tid >> 1, h = tid & 1;
    int lA = 2 * p, lB = 2 * p + 1;
    int nA = blockIdx.x * 128 + lA;
    int nB = nA + 1;
    bool vA = nA < NN, vB = nB < NN;

    const float4* aA = (const float4*)(g_A + (size_t)nA * HID);
    const float4* aB = (const float4*)(g_A + (size_t)nB * HID);

    float accA[32], accB[32];
#pragma unroll
    for (int j = 0; j < 32; j++) { accA[j] = 0.f; accB[j] = 0.f; }

    // ---- phase 1: relu(A) @ W1b^T
    for (int k4 = 0; k4 < HID / 4; k4++) {
        float4 a4 = vA ? aA[k4] : make_float4(0.f, 0.f, 0.f, 0.f);
        float4 b4 = vB ? aB[k4] : make_float4(0.f, 0.f, 0.f, 0.f);
        a4.x = fmaxf(a4.x, 0.f); a4.y = fmaxf(a4.y, 0.f);
        a4.z = fmaxf(a4.z, 0.f); a4.w = fmaxf(a4.w, 0.f);
        b4.x = fmaxf(b4.x, 0.f); b4.y = fmaxf(b4.y, 0.f);
        b4.z = fmaxf(b4.z, 0.f); b4.w = fmaxf(b4.w, 0.f);
#pragma unroll
        for (int s = 0; s < 4; s++) {
            float xa = (s == 0) ? a4.x : (s == 1) ? a4.y : (s == 2) ? a4.z : a4.w;
            float xb = (s == 0) ? b4.x : (s == 1) ? b4.y : (s == 2) ? b4.z : b4.w;
            const float4* wr = (const float4*)(Wt + (4 * k4 + s) * HID + 32 * h);
#pragma unroll
            for (int f4 = 0; f4 < 8; f4++) {
                float4 w = wr[f4];
                accA[4*f4+0] = fmaf(xa, w.x, accA[4*f4+0]);
                accA[4*f4+1] = fmaf(xa, w.y, accA[4*f4+1]);
                accA[4*f4+2] = fmaf(xa, w.z, accA[4*f4+2]);
                accA[4*f4+3] = fmaf(xa, w.w, accA[4*f4+3]);
                accB[4*f4+0] = fmaf(xb, w.x, accB[4*f4+0]);
                accB[4*f4+1] = fmaf(xb, w.y, accB[4*f4+1]);
                accB[4*f4+2] = fmaf(xb, w.z, accB[4*f4+2]);
                accB[4*f4+3] = fmaf(xb, w.w, accB[4*f4+3]);
            }
        }
    }

    // bn1 + relu -> transposed SMEM H tile
#pragma unroll
    for (int j = 0; j < 32; j++) {
        int f = 32 * h + j;
        Hs[f * HS_W + lA] = fmaxf(fmaf(accA[j], sc[f], sh[f]), 0.f);
        Hs[f * HS_W + lB] = fmaxf(fmaf(accB[j], sc[f], sh[f]), 0.f);
    }
    __syncthreads();

    // swap weights: Wt <- W2a^T
    for (int i = tid; i < HID * HID; i += 128) {
        int k = i >> 6, f = i & 63;
        Wt[k * HID + f] = W2a[f * HID + k];
    }
    __syncthreads();

    // ---- phase 2: Y2 = H1 @ W2a^T
    float acc2A[32], acc2B[32];
#pragma unroll
    for (int j = 0; j < 32; j++) { acc2A[j] = 0.f; acc2B[j] = 0.f; }

#pragma unroll 8
    for (int k = 0; k < HID; k++) {
        float xa = Hs[k * HS_W + lA];
        float xb = Hs[k * HS_W + lB];
        const float4* wr = (const float4*)(Wt + k * HID + 32 * h);
#pragma unroll
        for (int f4 = 0; f4 < 8; f4++) {
            float4 w = wr[f4];
            acc2A[4*f4+0] = fmaf(xa, w.x, acc2A[4*f4+0]);
            acc2A[4*f4+1] = fmaf(xa, w.y, acc2A[4*f4+1]);
            acc2A[4*f4+2] = fmaf(xa, w.z, acc2A[4*f4+2]);
            acc2A[4*f4+3] = fmaf(xa, w.w, acc2A[4*f4+3]);
            acc2B[4*f4+0] = fmaf(xb, w.x, acc2B[4*f4+0]);
            acc2B[4*f4+1] = fmaf(xb, w.y, acc2B[4*f4+1]);
            acc2B[4*f4+2] = fmaf(xb, w.z, acc2B[4*f4+2]);
            acc2B[4*f4+3] = fmaf(xb, w.w, acc2B[4*f4+3]);
        }
    }

    if (vA) {
        float4* Yo = (float4*)(g_Y + (size_t)nA * HID + 32 * h);
        float4* Ao = (float4*)(g_A + (size_t)nA * HID + 32 * h);
#pragma unroll
        for (int f4 = 0; f4 < 8; f4++) {
            float4 v = make_float4(acc2A[4*f4], acc2A[4*f4+1], acc2A[4*f4+2], acc2A[4*f4+3]);
            Yo[f4] = v;
            int fb = 32 * h + 4 * f4;
            Ao[f4] = make_float4(v.x + bs2[fb], v.y + bs2[fb+1], v.z + bs2[fb+2], v.w + bs2[fb+3]);
        }
    }
    if (vB) {
        float4* Yo = (float4*)(g_Y + (size_t)nB * HID + 32 * h);
        float4* Ao = (float4*)(g_A + (size_t)nB * HID + 32 * h);
#pragma unroll
        for (int f4 = 0; f4 < 8; f4++) {
            float4 v = make_float4(acc2B[4*f4], acc2B[4*f4+1], acc2B[4*f4+2], acc2B[4*f4+3]);
            Yo[f4] = v;
            int fb = 32 * h + 4 * f4;
            Ao[f4] = make_float4(v.x + bs2[fb], v.y + bs2[fb+1], v.z + bs2[fb+2], v.w + bs2[fb+3]);
        }
    }
}

// ------------------------------------------------- K5: final MLP + bn2 + relu + mean-pool (sum part)
__global__ __launch_bounds__(256) void k_final(
    const float* __restrict__ W, const float* __restrict__ bb,
    const float* __restrict__ ga, const float* __restrict__ be,
    const float* __restrict__ mm, const float* __restrict__ vv,
    const int* __restrict__ batch, float* __restrict__ out)
{
    __shared__ float Wt[HID][HID];
    __shared__ float sc[HID], sh[HID];
    for (int i = threadIdx.x; i < HID * HID; i += 256) {
        int k = i >> 6, f = i & 63;
        Wt[k][f] = W[f * HID + k];
    }
    if (threadIdx.x < HID) {
        int f = threadIdx.x;
        float s = ga[f] * rsqrtf(vv[f] + BN_EPS_F);
        sc[f] = s;
        sh[f] = (bb[f] - mm[f]) * s + be[f];
    }
    __syncthreads();

    int node = blockIdx.x * 256 + threadIdx.x;
    if (node >= NN) return;   // N % 32 == 0: whole warps exit together

    const float4* ar = (const float4*)(g_A + (size_t)node * HID);
    float acc[HID];
#pragma unroll
    for (int f = 0; f < HID; f++) acc[f] = 0.f;

    for (int k4 = 0; k4 < HID / 4; k4++) {
        float4 av = ar[k4];
        av.x = fmaxf(av.x, 0.f); av.y = fmaxf(av.y, 0.f);
        av.z = fmaxf(av.z, 0.f); av.w = fmaxf(av.w, 0.f);
#pragma unroll
        for (int s = 0; s < 4; s++) {
            float xs = (s == 0) ? av.x : ((s == 1) ? av.y : ((s == 2) ? av.z : av.w));
            const float4* wr = (const float4*)Wt[4 * k4 + s];
#pragma unroll
            for (int f4 = 0; f4 < 16; f4++) {
                float4 w = wr[f4];
                acc[4*f4+0] = fmaf(xs, w.x, acc[4*f4+0]);
                acc[4*f4+1] = fmaf(xs, w.y, acc[4*f4+1]);
                acc[4*f4+2] = fmaf(xs, w.z, acc[4*f4+2]);
                acc[4*f4+3] = fmaf(xs, w.w, acc[4*f4+3]);
            }
        }
    }

#pragma unroll
    for (int j = 0; j < HID; j++)
        acc[j] = fmaxf(fmaf(acc[j], sc[j], sh[j]), 0.f);

    int g = batch[node];
    int lane = threadIdx.x & 31;
    int g0 = __shfl_sync(0xffffffffu, g, 0);
    bool uni = __all_sync(0xffffffffu, g == g0);

    if (uni) {
#pragma unroll
        for (int j = 0; j < HID; j++) {
            float v = acc[j];
            v += __shfl_xor_sync(0xffffffffu, v, 1);
            v += __shfl_xor_sync(0xffffffffu, v, 2);
            v += __shfl_xor_sync(0xffffffffu, v, 4);
            v += __shfl_xor_sync(0xffffffffu, v, 8);
            v += __shfl_xor_sync(0xffffffffu, v, 16);
            acc[j] = v;
        }
        float* base = out + (size_t)g * HID;
#pragma unroll
        for (int j4 = 0; j4 < 16; j4++) {
            if (lane == j4)
                red_add_v4(base + 4 * j4, acc[4*j4], acc[4*j4+1], acc[4*j4+2], acc[4*j4+3]);
        }
    } else {
        float* base = out + (size_t)g * HID;
#pragma unroll
        for (int j4 = 0; j4 < 16; j4++)
            red_add_v4(base + 4 * j4, acc[4*j4], acc[4*j4+1], acc[4*j4+2], acc[4*j4+3]);
    }
}

// ------------------------------------------------- K6: divide by per-graph counts
__global__ void k_div(const int* __restrict__ batch, float* __restrict__ out)
{
    int g = blockIdx.x;
    __shared__ int cnt;
    if (threadIdx.x == 0) {
        int lo = 0, hi = NN;
        while (lo < hi) { int mid = (lo + hi) >> 1; if (batch[mid] < g) lo = mid + 1; else hi = mid; }
        int lo2 = lo, hi2 = NN;
        while (lo2 < hi2) { int mid = (lo2 + hi2) >> 1; if (batch[mid] < g + 1) lo2 = mid + 1; else hi2 = mid; }
        cnt = lo2 - lo;
    }
    __syncthreads();
    float c = (float)(cnt > 1 ? cnt : 1);
    out[(size_t)g * HID + threadIdx.x] /= c;
}

// ---------------------------------------------------------------- launch
extern "C" void kernel_launch(void* const* d_in, const int* in_sizes, int n_in,
                              void* d_out, int out_size)
{
    (void)in_sizes; (void)n_in; (void)out_size;
    const float* x    = (const float*)d_in[0];
    const int*   ei   = (const int*)d_in[1];
    const int*   batch= (const int*)d_in[2];
    const float* W1a  = (const float*)d_in[3];
    const float* b1a  = (const float*)d_in[4];
    const float* W1b  = (const float*)d_in[5];
    const float* b1b  = (const float*)d_in[6];
    const float* g1   = (const float*)d_in[7];
    const float* be1  = (const float*)d_in[8];
    const float* m1   = (const float*)d_in[9];
    const float* v1   = (const float*)d_in[10];
    const float* W2a  = (const float*)d_in[11];
    const float* b2a  = (const float*)d_in[12];
    const float* W2b  = (const float*)d_in[13];
    const float* b2b  = (const float*)d_in[14];
    const float* g2   = (const float*)d_in[15];
    const float* be2  = (const float*)d_in[16];
    const float* m2   = (const float*)d_in[17];
    const float* v2   = (const float*)d_in[18];
    float* out = (float*)d_out;

    const int midSmem = (HID * HID + HID * HS_W + 3 * HID) * (int)sizeof(float);  // ~50.4KB
    cudaFuncSetAttribute(k_mid, cudaFuncAttributeMaxDynamicSharedMemorySize, midSmem);

    int nodeBlocks128 = (NN + 127) / 128;          // 782
    int nodeBlocks256 = (NN + 255) / 256;          // 391
    int edgeBlocks = (EE * 16) / 256;              // 100000, exact

    k_zero<<<(NG * HID + 255) / 256, 256>>>(out, NG * HID);
    k_in_proj<<<nodeBlocks128, 128>>>(x, W1a, b1a);
    k_scatter<<<edgeBlocks, 256>>>(ei);
    k_mid<<<nodeBlocks128, 128, midSmem>>>(W1b, b1b, g1, be1, m1, v1, W2a, b2a);
    k_scatter<<<edgeBlocks, 256>>>(ei);
    k_final<<<nodeBlocks256, 256>>>(W2b, b2b, g2, be2, m2, v2, batch, out);
    k_div<<<NG, HID>>>(batch, out);
}

// round 3
// speedup vs baseline: 1.3048x; 1.3048x over previous
#include <cuda_runtime.h>
#include <cstdint>

#define NN 100000
#define EE 1600000
#define FIN 128
#define HID 64
#define NG 512
#define BN_EPS_F 1e-5f

#define SCAN_CHUNK 1024
#define NCHUNK ((NN + SCAN_CHUNK - 1) / SCAN_CHUNK)   // 98

// Scratch (allocation-free rule: __device__ globals).
__device__ __align__(16) float g_Y[(size_t)NN * HID];   // projected rows (gather source)
__device__ __align__(16) float g_A[(size_t)NN * HID];   // self + bias + aggregate
__device__ int g_cnt[NN];          // in-degree histogram
__device__ int g_scan[NN];         // per-chunk inclusive scans
__device__ int g_bsum[NCHUNK];     // chunk sums
__device__ int g_boff[NCHUNK];     // exclusive chunk offsets
__device__ int g_rowptr[NN + 1];   // CSR row pointers (by dst)
__device__ int g_cursor[NN];       // fill cursors for reorder
__device__ int g_ss[EE];           // src indices sorted by dst

__device__ __forceinline__ void red_add_v4(float* p, float a, float b, float c, float d) {
    asm volatile("red.global.add.v4.f32 [%0], {%1,%2,%3,%4};"
                 :: "l"(p), "f"(a), "f"(b), "f"(c), "f"(d) : "memory");
}

// ---------------------------------------------------------------- small utils
__global__ void k_zero_f(float* __restrict__ p, int n) {
    int i = blockIdx.x * blockDim.x + threadIdx.x;
    if (i < n) p[i] = 0.f;
}
__global__ void k_zero_i(int* __restrict__ p, int n) {
    int i = blockIdx.x * blockDim.x + threadIdx.x;
    if (i < n) p[i] = 0;
}

// ---------------------------------------------------------------- CSR build
__global__ void k_hist(const int* __restrict__ ei) {
    int e = blockIdx.x * blockDim.x + threadIdx.x;
    if (e < EE) atomicAdd(&g_cnt[ei[EE + e]], 1);
}

// pass1: per-chunk inclusive scan (Hillis-Steele in smem) + chunk sums
__global__ __launch_bounds__(SCAN_CHUNK) void k_scan1() {
    __shared__ int s[SCAN_CHUNK];
    int tid = threadIdx.x;
    int i = blockIdx.x * SCAN_CHUNK + tid;
    int v = (i < NN) ? g_cnt[i] : 0;
    s[tid] = v;
    __syncthreads();
#pragma unroll
    for (int off = 1; off < SCAN_CHUNK; off <<= 1) {
        int t = (tid >= off) ? s[tid - off] : 0;
        __syncthreads();
        s[tid] += t;
        __syncthreads();
    }
    if (i < NN) g_scan[i] = s[tid];
    if (tid == SCAN_CHUNK - 1) g_bsum[blockIdx.x] = s[tid];
}

// pass2: exclusive scan of chunk sums (small, serial in smem)
__global__ void k_scan2() {
    __shared__ int s[NCHUNK];
    int tid = threadIdx.x;
    if (tid < NCHUNK) s[tid] = g_bsum[tid];
    __syncthreads();
    if (tid == 0) {
        int run = 0;
        for (int c = 0; c < NCHUNK; c++) { int t = s[c]; s[c] = run; run += t; }
    }
    __syncthreads();
    if (tid < NCHUNK) g_boff[tid] = s[tid];
}

// pass3: finalize rowptr + cursor
__global__ void k_scan3() {
    int i = blockIdx.x * blockDim.x + threadIdx.x;
    if (i >= NN) return;
    int incl = g_scan[i] + g_boff[i / SCAN_CHUNK];
    g_rowptr[i + 1] = incl;
    g_cursor[i] = incl - g_cnt[i];
    if (i == 0) g_rowptr[0] = 0;
}

__global__ void k_reorder(const int* __restrict__ ei) {
    int e = blockIdx.x * blockDim.x + threadIdx.x;
    if (e >= EE) return;
    int d = ei[EE + e];
    int pos = atomicAdd(&g_cursor[d], 1);
    g_ss[pos] = ei[e];
}

// ---------------------------------------------------------------- aggregation
// A[n] = Y[n] + bias + sum_{e in row(n)} Y[ss[e]]
// 16 threads per node, one float4 per thread; gather-only (no atomics).
__global__ __launch_bounds__(256) void k_agg(const float* __restrict__ b) {
    int t = blockIdx.x * 256 + threadIdx.x;
    int n = t >> 4;
    int lane = t & 15;
    if (n >= NN) return;

    const float4* Y4 = (const float4*)g_Y;
    float4 bv = ((const float4*)b)[lane];
    float4 acc = Y4[(size_t)n * 16 + lane];
    acc.x += bv.x; acc.y += bv.y; acc.z += bv.z; acc.w += bv.w;

    int beg = g_rowptr[n], end = g_rowptr[n + 1];
#pragma unroll 4
    for (int e = beg; e < end; e++) {
        int s = g_ss[e];
        float4 v = Y4[(size_t)s * 16 + lane];
        acc.x += v.x; acc.y += v.y; acc.z += v.z; acc.w += v.w;
    }
    ((float4*)g_A)[(size_t)n * 16 + lane] = acc;
}

// ------------------------------------------------- K1: Y = x @ W1a^T (round-1 form, no bias/A write)
__global__ __launch_bounds__(256) void k_in_proj(
    const float* __restrict__ x, const float* __restrict__ W)
{
    __shared__ float Wt[FIN][HID];   // Wt[k][f] = W[f][k]
    for (int i = threadIdx.x; i < FIN * HID; i += 256) {
        int k = i >> 6, f = i & 63;
        Wt[k][f] = W[f * FIN + k];
    }
    __syncthreads();

    int node = blockIdx.x * 256 + threadIdx.x;
    if (node >= NN) return;

    const float4* xr = (const float4*)(x + (size_t)node * FIN);
    float acc[HID];
#pragma unroll
    for (int f = 0; f < HID; f++) acc[f] = 0.f;

    for (int k4 = 0; k4 < FIN / 4; k4++) {
        float4 xv = xr[k4];
#pragma unroll
        for (int s = 0; s < 4; s++) {
            float xs = (s == 0) ? xv.x : ((s == 1) ? xv.y : ((s == 2) ? xv.z : xv.w));
            const float4* wr = (const float4*)Wt[4 * k4 + s];
#pragma unroll
            for (int f4 = 0; f4 < 16; f4++) {
                float4 w = wr[f4];
                acc[4*f4+0] = fmaf(xs, w.x, acc[4*f4+0]);
                acc[4*f4+1] = fmaf(xs, w.y, acc[4*f4+1]);
                acc[4*f4+2] = fmaf(xs, w.z, acc[4*f4+2]);
                acc[4*f4+3] = fmaf(xs, w.w, acc[4*f4+3]);
            }
        }
    }

    float4* Yo = (float4*)(g_Y + (size_t)node * HID);
#pragma unroll
    for (int f4 = 0; f4 < 16; f4++)
        Yo[f4] = make_float4(acc[4*f4], acc[4*f4+1], acc[4*f4+2], acc[4*f4+3]);
}

// ------------------------------------------------- K3a: H1 = relu(bn1(relu(A1) @ W1b^T + b1b)) -> g_Y
__global__ __launch_bounds__(256) void k_mlp_a(
    const float* __restrict__ W, const float* __restrict__ bb,
    const float* __restrict__ ga, const float* __restrict__ be,
    const float* __restrict__ mm, const float* __restrict__ vv)
{
    __shared__ float Wt[HID][HID];
    __shared__ float sc[HID], sh[HID];
    for (int i = threadIdx.x; i < HID * HID; i += 256) {
        int k = i >> 6, f = i & 63;
        Wt[k][f] = W[f * HID + k];
    }
    if (threadIdx.x < HID) {
        int f = threadIdx.x;
        float s = ga[f] * rsqrtf(vv[f] + BN_EPS_F);
        sc[f] = s;
        sh[f] = (bb[f] - mm[f]) * s + be[f];
    }
    __syncthreads();

    int node = blockIdx.x * 256 + threadIdx.x;
    if (node >= NN) return;

    const float4* ar = (const float4*)(g_A + (size_t)node * HID);
    float acc[HID];
#pragma unroll
    for (int f = 0; f < HID; f++) acc[f] = 0.f;

    for (int k4 = 0; k4 < HID / 4; k4++) {
        float4 av = ar[k4];
        av.x = fmaxf(av.x, 0.f); av.y = fmaxf(av.y, 0.f);
        av.z = fmaxf(av.z, 0.f); av.w = fmaxf(av.w, 0.f);
#pragma unroll
        for (int s = 0; s < 4; s++) {
            float xs = (s == 0) ? av.x : ((s == 1) ? av.y : ((s == 2) ? av.z : av.w));
            const float4* wr = (const float4*)Wt[4 * k4 + s];
#pragma unroll
            for (int f4 = 0; f4 < 16; f4++) {
                float4 w = wr[f4];
                acc[4*f4+0] = fmaf(xs, w.x, acc[4*f4+0]);
                acc[4*f4+1] = fmaf(xs, w.y, acc[4*f4+1]);
                acc[4*f4+2] = fmaf(xs, w.z, acc[4*f4+2]);
                acc[4*f4+3] = fmaf(xs, w.w, acc[4*f4+3]);
            }
        }
    }

    float4* Ho = (float4*)(g_Y + (size_t)node * HID);
#pragma unroll
    for (int f4 = 0; f4 < 16; f4++) {
        float4 h;
        h.x = fmaxf(fmaf(acc[4*f4+0], sc[4*f4+0], sh[4*f4+0]), 0.f);
        h.y = fmaxf(fmaf(acc[4*f4+1], sc[4*f4+1], sh[4*f4+1]), 0.f);
        h.z = fmaxf(fmaf(acc[4*f4+2], sc[4*f4+2], sh[4*f4+2]), 0.f);
        h.w = fmaxf(fmaf(acc[4*f4+3], sc[4*f4+3], sh[4*f4+3]), 0.f);
        Ho[f4] = h;
    }
}

// ------------------------------------------------- K3b: Y2 = H1 @ W2a^T (in place in g_Y)
__global__ __launch_bounds__(256) void k_proj_h(const float* __restrict__ W)
{
    __shared__ float Wt[HID][HID];
    for (int i = threadIdx.x; i < HID * HID; i += 256) {
        int k = i >> 6, f = i & 63;
        Wt[k][f] = W[f * HID + k];
    }
    __syncthreads();

    int node = blockIdx.x * 256 + threadIdx.x;
    if (node >= NN) return;

    const float4* hr = (const float4*)(g_Y + (size_t)node * HID);
    float acc[HID];
#pragma unroll
    for (int f = 0; f < HID; f++) acc[f] = 0.f;

    for (int k4 = 0; k4 < HID / 4; k4++) {
        float4 hv = hr[k4];
#pragma unroll
        for (int s = 0; s < 4; s++) {
            float xs = (s == 0) ? hv.x : ((s == 1) ? hv.y : ((s == 2) ? hv.z : hv.w));
            const float4* wr = (const float4*)Wt[4 * k4 + s];
#pragma unroll
            for (int f4 = 0; f4 < 16; f4++) {
                float4 w = wr[f4];
                acc[4*f4+0] = fmaf(xs, w.x, acc[4*f4+0]);
                acc[4*f4+1] = fmaf(xs, w.y, acc[4*f4+1]);
                acc[4*f4+2] = fmaf(xs, w.z, acc[4*f4+2]);
                acc[4*f4+3] = fmaf(xs, w.w, acc[4*f4+3]);
            }
        }
    }

    float4* Yo = (float4*)(g_Y + (size_t)node * HID);
#pragma unroll
    for (int f4 = 0; f4 < 16; f4++)
        Yo[f4] = make_float4(acc[4*f4], acc[4*f4+1], acc[4*f4+2], acc[4*f4+3]);
}

// ------------------------------------------------- K5: final MLP + bn2 + relu + mean-pool (sum part)
__global__ __launch_bounds__(256) void k_final(
    const float* __restrict__ W, const float* __restrict__ bb,
    const float* __restrict__ ga, const float* __restrict__ be,
    const float* __restrict__ mm, const float* __restrict__ vv,
    const int* __restrict__ batch, float* __restrict__ out)
{
    __shared__ float Wt[HID][HID];
    __shared__ float sc[HID], sh[HID];
    for (int i = threadIdx.x; i < HID * HID; i += 256) {
        int k = i >> 6, f = i & 63;
        Wt[k][f] = W[f * HID + k];
    }
    if (threadIdx.x < HID) {
        int f = threadIdx.x;
        float s = ga[f] * rsqrtf(vv[f] + BN_EPS_F);
        sc[f] = s;
        sh[f] = (bb[f] - mm[f]) * s + be[f];
    }
    __syncthreads();

    int node = blockIdx.x * 256 + threadIdx.x;
    if (node >= NN) return;   // N % 32 == 0: whole warps exit together

    const float4* ar = (const float4*)(g_A + (size_t)node * HID);
    float acc[HID];
#pragma unroll
    for (int f = 0; f < HID; f++) acc[f] = 0.f;

    for (int k4 = 0; k4 < HID / 4; k4++) {
        float4 av = ar[k4];
        av.x = fmaxf(av.x, 0.f); av.y = fmaxf(av.y, 0.f);
        av.z = fmaxf(av.z, 0.f); av.w = fmaxf(av.w, 0.f);
#pragma unroll
        for (int s = 0; s < 4; s++) {
            float xs = (s == 0) ? av.x : ((s == 1) ? av.y : ((s == 2) ? av.z : av.w));
            const float4* wr = (const float4*)Wt[4 * k4 + s];
#pragma unroll
            for (int f4 = 0; f4 < 16; f4++) {
                float4 w = wr[f4];
                acc[4*f4+0] = fmaf(xs, w.x, acc[4*f4+0]);
                acc[4*f4+1] = fmaf(xs, w.y, acc[4*f4+1]);
                acc[4*f4+2] = fmaf(xs, w.z, acc[4*f4+2]);
                acc[4*f4+3] = fmaf(xs, w.w, acc[4*f4+3]);
            }
        }
    }

#pragma unroll
    for (int j = 0; j < HID; j++)
        acc[j] = fmaxf(fmaf(acc[j], sc[j], sh[j]), 0.f);

    int g = batch[node];
    int lane = threadIdx.x & 31;
    int g0 = __shfl_sync(0xffffffffu, g, 0);
    bool uni = __all_sync(0xffffffffu, g == g0);

    if (uni) {
#pragma unroll
        for (int j = 0; j < HID; j++) {
            float v = acc[j];
            v += __shfl_xor_sync(0xffffffffu, v, 1);
            v += __shfl_xor_sync(0xffffffffu, v, 2);
            v += __shfl_xor_sync(0xffffffffu, v, 4);
            v += __shfl_xor_sync(0xffffffffu, v, 8);
            v += __shfl_xor_sync(0xffffffffu, v, 16);
            acc[j] = v;
        }
        float* base = out + (size_t)g * HID;
#pragma unroll
        for (int j4 = 0; j4 < 16; j4++) {
            if (lane == j4)
                red_add_v4(base + 4*j4, acc[4*j4], acc[4*j4+1], acc[4*j4+2], acc[4*j4+3]);
        }
    } else {
        float* base = out + (size_t)g * HID;
#pragma unroll
        for (int j4 = 0; j4 < 16; j4++)
            red_add_v4(base + 4*j4, acc[4*j4], acc[4*j4+1], acc[4*j4+2], acc[4*j4+3]);
    }
}

// ------------------------------------------------- K6: divide by per-graph counts
__global__ void k_div(const int* __restrict__ batch, float* __restrict__ out)
{
    int g = blockIdx.x;
    __shared__ int cnt;
    if (threadIdx.x == 0) {
        int lo = 0, hi = NN;
        while (lo < hi) { int mid = (lo + hi) >> 1; if (batch[mid] < g) lo = mid + 1; else hi = mid; }
        int lo2 = lo, hi2 = NN;
        while (lo2 < hi2) { int mid = (lo2 + hi2) >> 1; if (batch[mid] < g + 1) lo2 = mid + 1; else hi2 = mid; }
        cnt = lo2 - lo;
    }
    __syncthreads();
    float c = (float)(cnt > 1 ? cnt : 1);
    out[(size_t)g * HID + threadIdx.x] /= c;
}

// ---------------------------------------------------------------- launch
extern "C" void kernel_launch(void* const* d_in, const int* in_sizes, int n_in,
                              void* d_out, int out_size)
{
    (void)in_sizes; (void)n_in; (void)out_size;
    const float* x    = (const float*)d_in[0];
    const int*   ei   = (const int*)d_in[1];
    const int*   batch= (const int*)d_in[2];
    const float* W1a  = (const float*)d_in[3];
    const float* b1a  = (const float*)d_in[4];
    const float* W1b  = (const float*)d_in[5];
    const float* b1b  = (const float*)d_in[6];
    const float* g1   = (const float*)d_in[7];
    const float* be1  = (const float*)d_in[8];
    const float* m1   = (const float*)d_in[9];
    const float* v1   = (const float*)d_in[10];
    const float* W2a  = (const float*)d_in[11];
    const float* b2a  = (const float*)d_in[12];
    const float* W2b  = (const float*)d_in[13];
    const float* b2b  = (const float*)d_in[14];
    const float* g2   = (const float*)d_in[15];
    const float* be2  = (const float*)d_in[16];
    const float* m2   = (const float*)d_in[17];
    const float* v2   = (const float*)d_in[18];
    float* out = (float*)d_out;

    int* cntP; cudaGetSymbolAddress((void**)&cntP, g_cnt);

    int nodeBlocks = (NN + 255) / 256;             // 391
    int edgeBlocks = (EE + 255) / 256;             // 6250
    int aggBlocks  = (NN * 16 + 255) / 256;        // 6250

    // CSR build (once, reused by both layers) — overlaps nothing but is cheap
    k_zero_i<<<(NN + 255) / 256, 256>>>(cntP, NN);
    k_zero_f<<<(NG * HID + 255) / 256, 256>>>(out, NG * HID);
    k_hist<<<edgeBlocks, 256>>>(ei);
    k_scan1<<<NCHUNK, SCAN_CHUNK>>>();
    k_scan2<<<1, 128>>>();
    k_scan3<<<(NN + 255) / 256, 256>>>();
    k_reorder<<<edgeBlocks, 256>>>(ei);

    // layer 1
    k_in_proj<<<nodeBlocks, 256>>>(x, W1a);
    k_agg<<<aggBlocks, 256>>>(b1a);
    k_mlp_a<<<nodeBlocks, 256>>>(W1b, b1b, g1, be1, m1, v1);

    // layer 2
    k_proj_h<<<nodeBlocks, 256>>>(W2a);
    k_agg<<<aggBlocks, 256>>>(b2a);
    k_final<<<nodeBlocks, 256>>>(W2b, b2b, g2, be2, m2, v2, batch, out);
    k_div<<<NG, HID>>>(batch, out);
}

// round 4
// speedup vs baseline: 1.4735x; 1.1293x over previous
#include <cuda_runtime.h>
#include <cstdint>

#define NN 100000
#define EE 1600000
#define FIN 128
#define HID 64
#define NG 512
#define BN_EPS_F 1e-5f

#define SCAN_CHUNK 1024
#define NCHUNK ((NN + SCAN_CHUNK - 1) / SCAN_CHUNK)   // 98

// GEMM tiling
#define MT 128
#define NT 64
#define KC 64
#define MPAD 132

// Scratch (allocation-free rule: __device__ globals).
__device__ __align__(16) float g_Y[(size_t)NN * HID];   // projected rows (gather source)
__device__ __align__(16) float g_A[(size_t)NN * HID];   // self + bias + aggregate
__device__ int g_cnt[NN];
__device__ int g_scan[NN];
__device__ int g_bsum[NCHUNK];
__device__ int g_boff[NCHUNK];
__device__ int g_rowptr[NN + 1];
__device__ int g_cursor[NN];
__device__ int g_ss[EE];           // src indices sorted by dst

__device__ __forceinline__ void red_add_v4(float* p, float a, float b, float c, float d) {
    asm volatile("red.global.add.v4.f32 [%0], {%1,%2,%3,%4};"
                 :: "l"(p), "f"(a), "f"(b), "f"(c), "f"(d) : "memory");
}

// ---------------------------------------------------------------- small utils
__global__ void k_zero_f(float* __restrict__ p, int n) {
    int i = blockIdx.x * blockDim.x + threadIdx.x;
    if (i < n) p[i] = 0.f;
}
__global__ void k_zero_i(int* __restrict__ p, int n) {
    int i = blockIdx.x * blockDim.x + threadIdx.x;
    if (i < n) p[i] = 0;
}

// ---------------------------------------------------------------- CSR build
__global__ void k_hist(const int* __restrict__ ei) {
    int e = blockIdx.x * blockDim.x + threadIdx.x;
    if (e < EE) atomicAdd(&g_cnt[ei[EE + e]], 1);
}

__global__ __launch_bounds__(SCAN_CHUNK) void k_scan1() {
    __shared__ int s[SCAN_CHUNK];
    int tid = threadIdx.x;
    int i = blockIdx.x * SCAN_CHUNK + tid;
    int v = (i < NN) ? g_cnt[i] : 0;
    s[tid] = v;
    __syncthreads();
#pragma unroll
    for (int off = 1; off < SCAN_CHUNK; off <<= 1) {
        int t = (tid >= off) ? s[tid - off] : 0;
        __syncthreads();
        s[tid] += t;
        __syncthreads();
    }
    if (i < NN) g_scan[i] = s[tid];
    if (tid == SCAN_CHUNK - 1) g_bsum[blockIdx.x] = s[tid];
}

__global__ void k_scan2() {
    __shared__ int s[NCHUNK];
    int tid = threadIdx.x;
    if (tid < NCHUNK) s[tid] = g_bsum[tid];
    __syncthreads();
    if (tid == 0) {
        int run = 0;
        for (int c = 0; c < NCHUNK; c++) { int t = s[c]; s[c] = run; run += t; }
    }
    __syncthreads();
    if (tid < NCHUNK) g_boff[tid] = s[tid];
}

__global__ void k_scan3() {
    int i = blockIdx.x * blockDim.x + threadIdx.x;
    if (i >= NN) return;
    int incl = g_scan[i] + g_boff[i / SCAN_CHUNK];
    g_rowptr[i + 1] = incl;
    g_cursor[i] = incl - g_cnt[i];
    if (i == 0) g_rowptr[0] = 0;
}

__global__ void k_reorder(const int* __restrict__ ei) {
    int e = blockIdx.x * blockDim.x + threadIdx.x;
    if (e >= EE) return;
    int d = ei[EE + e];
    int pos = atomicAdd(&g_cursor[d], 1);
    g_ss[pos] = ei[e];
}

// ---------------------------------------------------------------- aggregation
// A[n] = Y[n] + bias + sum_{e in row(n)} Y[ss[e]]; 16 threads/node, gather-only.
__global__ __launch_bounds__(256) void k_agg(const float* __restrict__ b) {
    int t = blockIdx.x * 256 + threadIdx.x;
    int n = t >> 4;
    int lane = t & 15;
    if (n >= NN) return;

    const float4* Y4 = (const float4*)g_Y;
    float4 bv = ((const float4*)b)[lane];
    float4 acc = Y4[(size_t)n * 16 + lane];
    acc.x += bv.x; acc.y += bv.y; acc.z += bv.z; acc.w += bv.w;

    int beg = g_rowptr[n], end = g_rowptr[n + 1];
#pragma unroll 4
    for (int e = beg; e < end; e++) {
        int s = g_ss[e];
        float4 v = Y4[(size_t)s * 16 + lane];
        acc.x += v.x; acc.y += v.y; acc.z += v.z; acc.w += v.w;
    }
    ((float4*)g_A)[(size_t)n * 16 + lane] = acc;
}

// ---------------------------------------------------------------- tiled GEMM
// out_row[n] = act( (RELU_IN ? relu(Asrc[n]) : Asrc[n]) @ W^T ), act per EPI:
//   EPI 0: plain write to Yout
//   EPI 1: y = relu(acc*sc + sh)  -> Yout          (bn + bias folded)
//   EPI 2: y = relu(acc*sc + sh)  -> pool RED into out[batch[n]]
// Block 256 = 16(m-groups) x 16(n-groups); micro-tile 8 rows x 4 cols.
template<int K, bool RELU_IN, int EPI>
__global__ __launch_bounds__(256) void k_gemm(
    const float* __restrict__ Asrc, const float* __restrict__ W,
    float* __restrict__ Yout,
    const float* __restrict__ bb, const float* __restrict__ ga,
    const float* __restrict__ be, const float* __restrict__ mm,
    const float* __restrict__ vv,
    const int* __restrict__ batch, float* __restrict__ out)
{
    extern __shared__ float sm[];
    float* Ws = sm;                         // [K][NT]  Ws[k*NT+n] = W[n][k]
    float* As = Ws + K * NT;                // [KC][MPAD] transposed A chunk
    float* sc = As + KC * MPAD;
    float* sh = sc + NT;

    int tid = threadIdx.x;
    for (int i = tid; i < K * NT; i += 256) {
        int k = i >> 6, n = i & 63;
        Ws[k * NT + n] = W[n * K + k];
    }
    if (EPI >= 1 && tid < NT) {
        float s = ga[tid] * rsqrtf(vv[tid] + BN_EPS_F);
        sc[tid] = s;
        sh[tid] = (bb[tid] - mm[tid]) * s + be[tid];
    }

    int m0 = blockIdx.x * MT;
    int tm = tid >> 4, tn = tid & 15;

    float acc[8][4];
#pragma unroll
    for (int r = 0; r < 8; r++)
#pragma unroll
        for (int c = 0; c < 4; c++) acc[r][c] = 0.f;

#pragma unroll
    for (int kc = 0; kc < K / KC; kc++) {
        __syncthreads();   // Ws/sc ready (first iter) or As free (later iters)
        // load A chunk transposed: As[k][m] = Asrc[m0+m][kc*KC + k]
        for (int i = tid; i < MT * (KC / 4); i += 256) {
            int m = i >> 4;
            int q = i & 15;
            int gm = m0 + m;
            float4 v = make_float4(0.f, 0.f, 0.f, 0.f);
            if (gm < NN) v = ((const float4*)(Asrc + (size_t)gm * K))[kc * 16 + q];
            if (RELU_IN) {
                v.x = fmaxf(v.x, 0.f); v.y = fmaxf(v.y, 0.f);
                v.z = fmaxf(v.z, 0.f); v.w = fmaxf(v.w, 0.f);
            }
            As[(4 * q + 0) * MPAD + m] = v.x;
            As[(4 * q + 1) * MPAD + m] = v.y;
            As[(4 * q + 2) * MPAD + m] = v.z;
            As[(4 * q + 3) * MPAD + m] = v.w;
        }
        __syncthreads();

        const float* wbase = Ws + kc * KC * NT;
#pragma unroll 8
        for (int k = 0; k < KC; k++) {
            float4 a01 = *(const float4*)(As + k * MPAD + tm * 8);
            float4 a23 = *(const float4*)(As + k * MPAD + tm * 8 + 4);
            float4 w = *(const float4*)(wbase + k * NT + tn * 4);
            float av[8] = {a01.x, a01.y, a01.z, a01.w, a23.x, a23.y, a23.z, a23.w};
#pragma unroll
            for (int r = 0; r < 8; r++) {
                acc[r][0] = fmaf(av[r], w.x, acc[r][0]);
                acc[r][1] = fmaf(av[r], w.y, acc[r][1]);
                acc[r][2] = fmaf(av[r], w.z, acc[r][2]);
                acc[r][3] = fmaf(av[r], w.w, acc[r][3]);
            }
        }
    }

    // ---- epilogue
    if (EPI == 0) {
#pragma unroll
        for (int r = 0; r < 8; r++) {
            int gm = m0 + tm * 8 + r;
            if (gm < NN)
                *(float4*)(Yout + (size_t)gm * NT + tn * 4) =
                    make_float4(acc[r][0], acc[r][1], acc[r][2], acc[r][3]);
        }
    } else {
        float4 scv = *(const float4*)(sc + tn * 4);
        float4 shv = *(const float4*)(sh + tn * 4);
#pragma unroll
        for (int r = 0; r < 8; r++) {
            int gm = m0 + tm * 8 + r;
            if (gm >= NN) continue;
            float h0 = fmaxf(fmaf(acc[r][0], scv.x, shv.x), 0.f);
            float h1 = fmaxf(fmaf(acc[r][1], scv.y, shv.y), 0.f);
            float h2 = fmaxf(fmaf(acc[r][2], scv.z, shv.z), 0.f);
            float h3 = fmaxf(fmaf(acc[r][3], scv.w, shv.w), 0.f);
            if (EPI == 1) {
                *(float4*)(Yout + (size_t)gm * NT + tn * 4) = make_float4(h0, h1, h2, h3);
            } else {
                int g = batch[gm];
                red_add_v4(out + (size_t)g * NT + tn * 4, h0, h1, h2, h3);
            }
        }
    }
}

// ------------------------------------------------- divide by per-graph counts
__global__ void k_div(const int* __restrict__ batch, float* __restrict__ out)
{
    int g = blockIdx.x;
    __shared__ int cnt;
    if (threadIdx.x == 0) {
        int lo = 0, hi = NN;
        while (lo < hi) { int mid = (lo + hi) >> 1; if (batch[mid] < g) lo = mid + 1; else hi = mid; }
        int lo2 = lo, hi2 = NN;
        while (lo2 < hi2) { int mid = (lo2 + hi2) >> 1; if (batch[mid] < g + 1) lo2 = mid + 1; else hi2 = mid; }
        cnt = lo2 - lo;
    }
    __syncthreads();
    float c = (float)(cnt > 1 ? cnt : 1);
    out[(size_t)g * HID + threadIdx.x] /= c;
}

// ---------------------------------------------------------------- launch
extern "C" void kernel_launch(void* const* d_in, const int* in_sizes, int n_in,
                              void* d_out, int out_size)
{
    (void)in_sizes; (void)n_in; (void)out_size;
    const float* x    = (const float*)d_in[0];
    const int*   ei   = (const int*)d_in[1];
    const int*   batch= (const int*)d_in[2];
    const float* W1a  = (const float*)d_in[3];
    const float* b1a  = (const float*)d_in[4];
    const float* W1b  = (const float*)d_in[5];
    const float* b1b  = (const float*)d_in[6];
    const float* g1   = (const float*)d_in[7];
    const float* be1  = (const float*)d_in[8];
    const float* m1   = (const float*)d_in[9];
    const float* v1   = (const float*)d_in[10];
    const float* W2a  = (const float*)d_in[11];
    const float* b2a  = (const float*)d_in[12];
    const float* W2b  = (const float*)d_in[13];
    const float* b2b  = (const float*)d_in[14];
    const float* g2   = (const float*)d_in[15];
    const float* be2  = (const float*)d_in[16];
    const float* m2   = (const float*)d_in[17];
    const float* v2   = (const float*)d_in[18];
    float* out = (float*)d_out;

    float* yP;  cudaGetSymbolAddress((void**)&yP, g_Y);
    float* aP;  cudaGetSymbolAddress((void**)&aP, g_A);
    int* cntP;  cudaGetSymbolAddress((void**)&cntP, g_cnt);

    const int smem64  = (HID * NT + KC * MPAD + 2 * NT) * (int)sizeof(float);  // ~50.7KB
    const int smem128 = (FIN * NT + KC * MPAD + 2 * NT) * (int)sizeof(float);  // ~67.1KB
    cudaFuncSetAttribute(k_gemm<FIN, false, 0>, cudaFuncAttributeMaxDynamicSharedMemorySize, smem128);
    cudaFuncSetAttribute(k_gemm<HID, true, 1>,  cudaFuncAttributeMaxDynamicSharedMemorySize, smem64);
    cudaFuncSetAttribute(k_gemm<HID, false, 0>, cudaFuncAttributeMaxDynamicSharedMemorySize, smem64);
    cudaFuncSetAttribute(k_gemm<HID, true, 2>,  cudaFuncAttributeMaxDynamicSharedMemorySize, smem64);

    int gemmBlocks = (NN + MT - 1) / MT;           // 782
    int edgeBlocks = (EE + 255) / 256;             // 6250
    int aggBlocks  = (NN * 16 + 255) / 256;        // 6250

    // CSR build (reused by both layers)
    k_zero_i<<<(NN + 255) / 256, 256>>>(cntP, NN);
    k_zero_f<<<(NG * HID + 255) / 256, 256>>>(out, NG * HID);
    k_hist<<<edgeBlocks, 256>>>(ei);
    k_scan1<<<NCHUNK, SCAN_CHUNK>>>();
    k_scan2<<<1, 128>>>();
    k_scan3<<<(NN + 255) / 256, 256>>>();
    k_reorder<<<edgeBlocks, 256>>>(ei);

    // layer 1
    k_gemm<FIN, false, 0><<<gemmBlocks, 256, smem128>>>(
        x, W1a, yP, nullptr, nullptr, nullptr, nullptr, nullptr, nullptr, nullptr);
    k_agg<<<aggBlocks, 256>>>(b1a);
    k_gemm<HID, true, 1><<<gemmBlocks, 256, smem64>>>(
        aP, W1b, yP, b1b, g1, be1, m1, v1, nullptr, nullptr);

    // layer 2
    k_gemm<HID, false, 0><<<gemmBlocks, 256, smem64>>>(
        yP, W2a, yP, nullptr, nullptr, nullptr, nullptr, nullptr, nullptr, nullptr);
    k_agg<<<aggBlocks, 256>>>(b2a);
    k_gemm<HID, true, 2><<<gemmBlocks, 256, smem64>>>(
        aP, W2b, nullptr, b2b, g2, be2, m2, v2, batch, out);
    k_div<<<NG, HID>>>(batch, out);
}

// round 5
// speedup vs baseline: 1.4970x; 1.0160x over previous
#include <cuda_runtime.h>
#include <cstdint>

#define NN 100000
#define EE 1600000
#define FIN 128
#define HID 64
#define NG 512
#define BN_EPS_F 1e-5f

#define SCAN_CHUNK 1024
#define NCHUNK ((NN + SCAN_CHUNK - 1) / SCAN_CHUNK)   // 98

// GEMM tiling
#define MT 128
#define NT 64
#define KC 64
#define MPAD 132

// Scratch (allocation-free rule: __device__ globals).
__device__ __align__(16) float g_Y[(size_t)NN * HID];
__device__ __align__(16) float g_A[(size_t)NN * HID];
__device__ int g_cnt[NN];
__device__ int g_scan[NN];
__device__ int g_bsum[NCHUNK];
__device__ int g_rowptr[NN + 1];
__device__ int g_cursor[NN];
__device__ int g_ss[EE];

__device__ __forceinline__ void red_add_v4(float* p, float a, float b, float c, float d) {
    asm volatile("red.global.add.v4.f32 [%0], {%1,%2,%3,%4};"
                 :: "l"(p), "f"(a), "f"(b), "f"(c), "f"(d) : "memory");
}

// ---------------------------------------------------------------- fused zero
__global__ void k_zero_all(float* __restrict__ out) {
    int i = blockIdx.x * blockDim.x + threadIdx.x;
    if (i < NG * HID) out[i] = 0.f;
    if (i < NN) g_cnt[i] = 0;
}

// ---------------------------------------------------------------- CSR build
__global__ void k_hist(const int* __restrict__ ei) {
    int e = blockIdx.x * blockDim.x + threadIdx.x;
    if (e < EE) atomicAdd(&g_cnt[ei[EE + e]], 1);
}

__global__ __launch_bounds__(SCAN_CHUNK) void k_scan1() {
    __shared__ int s[SCAN_CHUNK];
    int tid = threadIdx.x;
    int i = blockIdx.x * SCAN_CHUNK + tid;
    int v = (i < NN) ? g_cnt[i] : 0;
    s[tid] = v;
    __syncthreads();
#pragma unroll
    for (int off = 1; off < SCAN_CHUNK; off <<= 1) {
        int t = (tid >= off) ? s[tid - off] : 0;
        __syncthreads();
        s[tid] += t;
        __syncthreads();
    }
    if (i < NN) g_scan[i] = s[tid];
    if (tid == SCAN_CHUNK - 1) g_bsum[blockIdx.x] = s[tid];
}

// fused scan2+scan3: every block redundantly scans the 98 chunk sums (cheap),
// then finalizes rowptr + cursor.
__global__ void k_scan3f() {
    __shared__ int boff[NCHUNK];
    if (threadIdx.x == 0) {
        int run = 0;
#pragma unroll 2
        for (int c = 0; c < NCHUNK; c++) { int t = g_bsum[c]; boff[c] = run; run += t; }
    }
    __syncthreads();
    int i = blockIdx.x * blockDim.x + threadIdx.x;
    if (i >= NN) return;
    int incl = g_scan[i] + boff[i / SCAN_CHUNK];
    g_rowptr[i + 1] = incl;
    g_cursor[i] = incl - g_cnt[i];
    if (i == 0) g_rowptr[0] = 0;
}

__global__ void k_reorder(const int* __restrict__ ei) {
    int e = blockIdx.x * blockDim.x + threadIdx.x;
    if (e >= EE) return;
    int d = ei[EE + e];
    int pos = atomicAdd(&g_cursor[d], 1);
    g_ss[pos] = ei[e];
}

// ---------------------------------------------------------------- aggregation
__global__ __launch_bounds__(256) void k_agg(const float* __restrict__ b) {
    int t = blockIdx.x * 256 + threadIdx.x;
    int n = t >> 4;
    int lane = t & 15;
    if (n >= NN) return;

    const float4* Y4 = (const float4*)g_Y;
    float4 bv = ((const float4*)b)[lane];
    float4 acc = Y4[(size_t)n * 16 + lane];
    acc.x += bv.x; acc.y += bv.y; acc.z += bv.z; acc.w += bv.w;

    int beg = g_rowptr[n], end = g_rowptr[n + 1];
#pragma unroll 4
    for (int e = beg; e < end; e++) {
        int s = g_ss[e];
        float4 v = Y4[(size_t)s * 16 + lane];
        acc.x += v.x; acc.y += v.y; acc.z += v.z; acc.w += v.w;
    }
    ((float4*)g_A)[(size_t)n * 16 + lane] = acc;
}

// ---------------------------------------------------------------- tiled GEMM (in_proj / final)
// EPI 0: plain write. EPI 2: bn+relu then pool-RED into out[batch[n]].
template<int K, bool RELU_IN, int EPI>
__global__ __launch_bounds__(256) void k_gemm(
    const float* __restrict__ Asrc, const float* __restrict__ W,
    float* __restrict__ Yout,
    const float* __restrict__ bb, const float* __restrict__ ga,
    const float* __restrict__ be, const float* __restrict__ mm,
    const float* __restrict__ vv,
    const int* __restrict__ batch, float* __restrict__ out)
{
    extern __shared__ float sm[];
    float* Ws = sm;                         // [K][NT]
    float* As = Ws + K * NT;                // [KC][MPAD]
    float* sc = As + KC * MPAD;
    float* sh = sc + NT;

    int tid = threadIdx.x;
    for (int i = tid; i < K * NT; i += 256) {
        int k = i >> 6, n = i & 63;
        Ws[k * NT + n] = W[n * K + k];
    }
    if (EPI == 2 && tid < NT) {
        float s = ga[tid] * rsqrtf(vv[tid] + BN_EPS_F);
        sc[tid] = s;
        sh[tid] = (bb[tid] - mm[tid]) * s + be[tid];
    }

    int m0 = blockIdx.x * MT;
    int tm = tid >> 4, tn = tid & 15;

    float acc[8][4];
#pragma unroll
    for (int r = 0; r < 8; r++)
#pragma unroll
        for (int c = 0; c < 4; c++) acc[r][c] = 0.f;

#pragma unroll
    for (int kc = 0; kc < K / KC; kc++) {
        __syncthreads();
        for (int i = tid; i < MT * (KC / 4); i += 256) {
            int m = i >> 4;
            int q = i & 15;
            int gm = m0 + m;
            float4 v = make_float4(0.f, 0.f, 0.f, 0.f);
            if (gm < NN) v = ((const float4*)(Asrc + (size_t)gm * K))[kc * 16 + q];
            if (RELU_IN) {
                v.x = fmaxf(v.x, 0.f); v.y = fmaxf(v.y, 0.f);
                v.z = fmaxf(v.z, 0.f); v.w = fmaxf(v.w, 0.f);
            }
            As[(4 * q + 0) * MPAD + m] = v.x;
            As[(4 * q + 1) * MPAD + m] = v.y;
            As[(4 * q + 2) * MPAD + m] = v.z;
            As[(4 * q + 3) * MPAD + m] = v.w;
        }
        __syncthreads();

        const float* wbase = Ws + kc * KC * NT;
#pragma unroll 8
        for (int k = 0; k < KC; k++) {
            float4 a01 = *(const float4*)(As + k * MPAD + tm * 8);
            float4 a23 = *(const float4*)(As + k * MPAD + tm * 8 + 4);
            float4 w = *(const float4*)(wbase + k * NT + tn * 4);
            float av[8] = {a01.x, a01.y, a01.z, a01.w, a23.x, a23.y, a23.z, a23.w};
#pragma unroll
            for (int r = 0; r < 8; r++) {
                acc[r][0] = fmaf(av[r], w.x, acc[r][0]);
                acc[r][1] = fmaf(av[r], w.y, acc[r][1]);
                acc[r][2] = fmaf(av[r], w.z, acc[r][2]);
                acc[r][3] = fmaf(av[r], w.w, acc[r][3]);
            }
        }
    }

    if (EPI == 0) {
#pragma unroll
        for (int r = 0; r < 8; r++) {
            int gm = m0 + tm * 8 + r;
            if (gm < NN)
                *(float4*)(Yout + (size_t)gm * NT + tn * 4) =
                    make_float4(acc[r][0], acc[r][1], acc[r][2], acc[r][3]);
        }
    } else {
        float4 scv = *(const float4*)(sc + tn * 4);
        float4 shv = *(const float4*)(sh + tn * 4);
#pragma unroll
        for (int r = 0; r < 8; r++) {
            int gm = m0 + tm * 8 + r;
            if (gm >= NN) continue;
            float h0 = fmaxf(fmaf(acc[r][0], scv.x, shv.x), 0.f);
            float h1 = fmaxf(fmaf(acc[r][1], scv.y, shv.y), 0.f);
            float h2 = fmaxf(fmaf(acc[r][2], scv.z, shv.z), 0.f);
            float h3 = fmaxf(fmaf(acc[r][3], scv.w, shv.w), 0.f);
            int g = batch[gm];
            red_add_v4(out + (size_t)g * NT + tn * 4, h0, h1, h2, h3);
        }
    }
}

// ---------------------------------------------------------------- k_mid: fused
//   H = relu(bn1(relu(A1) @ W1b^T + b1b));  Y2 = H @ W2a^T -> g_Y
// Phase-1 output tile (after bn+relu) is written back into the SMEM A-buffer
// transposed — exactly the phase-2 input layout.
__global__ __launch_bounds__(256) void k_mid(
    const float* __restrict__ W1b, const float* __restrict__ b1b,
    const float* __restrict__ g1,  const float* __restrict__ be1,
    const float* __restrict__ m1,  const float* __restrict__ v1,
    const float* __restrict__ W2a)
{
    extern __shared__ float sm[];
    float* Ws1 = sm;                        // [64][64]
    float* Ws2 = Ws1 + HID * NT;            // [64][64]
    float* As  = Ws2 + HID * NT;            // [KC][MPAD]
    float* sc  = As + KC * MPAD;
    float* sh  = sc + NT;

    int tid = threadIdx.x;
    for (int i = tid; i < HID * NT; i += 256) {
        int k = i >> 6, n = i & 63;
        Ws1[k * NT + n] = W1b[n * HID + k];
        Ws2[k * NT + n] = W2a[n * HID + k];
    }
    if (tid < NT) {
        float s = g1[tid] * rsqrtf(v1[tid] + BN_EPS_F);
        sc[tid] = s;
        sh[tid] = (b1b[tid] - m1[tid]) * s + be1[tid];
    }

    int m0 = blockIdx.x * MT;
    int tm = tid >> 4, tn = tid & 15;

    // load A chunk = relu(g_A rows), transposed
    for (int i = tid; i < MT * (KC / 4); i += 256) {
        int m = i >> 4;
        int q = i & 15;
        int gm = m0 + m;
        float4 v = make_float4(0.f, 0.f, 0.f, 0.f);
        if (gm < NN) v = ((const float4*)(g_A + (size_t)gm * HID))[q];
        v.x = fmaxf(v.x, 0.f); v.y = fmaxf(v.y, 0.f);
        v.z = fmaxf(v.z, 0.f); v.w = fmaxf(v.w, 0.f);
        As[(4 * q + 0) * MPAD + m] = v.x;
        As[(4 * q + 1) * MPAD + m] = v.y;
        As[(4 * q + 2) * MPAD + m] = v.z;
        As[(4 * q + 3) * MPAD + m] = v.w;
    }
    __syncthreads();

    float acc[8][4];
#pragma unroll
    for (int r = 0; r < 8; r++)
#pragma unroll
        for (int c = 0; c < 4; c++) acc[r][c] = 0.f;

    // phase 1
#pragma unroll 8
    for (int k = 0; k < KC; k++) {
        float4 a01 = *(const float4*)(As + k * MPAD + tm * 8);
        float4 a23 = *(const float4*)(As + k * MPAD + tm * 8 + 4);
        float4 w = *(const float4*)(Ws1 + k * NT + tn * 4);
        float av[8] = {a01.x, a01.y, a01.z, a01.w, a23.x, a23.y, a23.z, a23.w};
#pragma unroll
        for (int r = 0; r < 8; r++) {
            acc[r][0] = fmaf(av[r], w.x, acc[r][0]);
            acc[r][1] = fmaf(av[r], w.y, acc[r][1]);
            acc[r][2] = fmaf(av[r], w.z, acc[r][2]);
            acc[r][3] = fmaf(av[r], w.w, acc[r][3]);
        }
    }
    __syncthreads();   // all phase-1 reads of As complete

    // bn1 + relu -> write H tile back into As (transposed: As[n][m])
    {
        float4 scv = *(const float4*)(sc + tn * 4);
        float4 shv = *(const float4*)(sh + tn * 4);
#pragma unroll
        for (int r = 0; r < 8; r++) {
            int m = tm * 8 + r;
            As[(tn * 4 + 0) * MPAD + m] = fmaxf(fmaf(acc[r][0], scv.x, shv.x), 0.f);
            As[(tn * 4 + 1) * MPAD + m] = fmaxf(fmaf(acc[r][1], scv.y, shv.y), 0.f);
            As[(tn * 4 + 2) * MPAD + m] = fmaxf(fmaf(acc[r][2], scv.z, shv.z), 0.f);
            As[(tn * 4 + 3) * MPAD + m] = fmaxf(fmaf(acc[r][3], scv.w, shv.w), 0.f);
        }
    }
    __syncthreads();

    // phase 2
#pragma unroll
    for (int r = 0; r < 8; r++)
#pragma unroll
        for (int c = 0; c < 4; c++) acc[r][c] = 0.f;

#pragma unroll 8
    for (int k = 0; k < KC; k++) {
        float4 a01 = *(const float4*)(As + k * MPAD + tm * 8);
        float4 a23 = *(const float4*)(As + k * MPAD + tm * 8 + 4);
        float4 w = *(const float4*)(Ws2 + k * NT + tn * 4);
        float av[8] = {a01.x, a01.y, a01.z, a01.w, a23.x, a23.y, a23.z, a23.w};
#pragma unroll
        for (int r = 0; r < 8; r++) {
            acc[r][0] = fmaf(av[r], w.x, acc[r][0]);
            acc[r][1] = fmaf(av[r], w.y, acc[r][1]);
            acc[r][2] = fmaf(av[r], w.z, acc[r][2]);
            acc[r][3] = fmaf(av[r], w.w, acc[r][3]);
        }
    }

#pragma unroll
    for (int r = 0; r < 8; r++) {
        int gm = m0 + tm * 8 + r;
        if (gm < NN)
            *(float4*)(g_Y + (size_t)gm * HID + tn * 4) =
                make_float4(acc[r][0], acc[r][1], acc[r][2], acc[r][3]);
    }
}

// ------------------------------------------------- divide by per-graph counts
__global__ void k_div(const int* __restrict__ batch, float* __restrict__ out)
{
    int g = blockIdx.x;
    __shared__ int cnt;
    if (threadIdx.x == 0) {
        int lo = 0, hi = NN;
        while (lo < hi) { int mid = (lo + hi) >> 1; if (batch[mid] < g) lo = mid + 1; else hi = mid; }
        int lo2 = lo, hi2 = NN;
        while (lo2 < hi2) { int mid = (lo2 + hi2) >> 1; if (batch[mid] < g + 1) lo2 = mid + 1; else hi2 = mid; }
        cnt = lo2 - lo;
    }
    __syncthreads();
    float c = (float)(cnt > 1 ? cnt : 1);
    out[(size_t)g * HID + threadIdx.x] /= c;
}

// ---------------------------------------------------------------- launch
extern "C" void kernel_launch(void* const* d_in, const int* in_sizes, int n_in,
                              void* d_out, int out_size)
{
    (void)in_sizes; (void)n_in; (void)out_size;
    const float* x    = (const float*)d_in[0];
    const int*   ei   = (const int*)d_in[1];
    const int*   batch= (const int*)d_in[2];
    const float* W1a  = (const float*)d_in[3];
    const float* b1a  = (const float*)d_in[4];
    const float* W1b  = (const float*)d_in[5];
    const float* b1b  = (const float*)d_in[6];
    const float* g1   = (const float*)d_in[7];
    const float* be1  = (const float*)d_in[8];
    const float* m1   = (const float*)d_in[9];
    const float* v1   = (const float*)d_in[10];
    const float* W2a  = (const float*)d_in[11];
    const float* b2a  = (const float*)d_in[12];
    const float* W2b  = (const float*)d_in[13];
    const float* b2b  = (const float*)d_in[14];
    const float* g2   = (const float*)d_in[15];
    const float* be2  = (const float*)d_in[16];
    const float* m2   = (const float*)d_in[17];
    const float* v2   = (const float*)d_in[18];
    float* out = (float*)d_out;

    float* yP;  cudaGetSymbolAddress((void**)&yP, g_Y);
    float* aP;  cudaGetSymbolAddress((void**)&aP, g_A);

    const int smem64  = (HID * NT + KC * MPAD + 2 * NT) * (int)sizeof(float);      // ~50.7KB
    const int smem128 = (FIN * NT + KC * MPAD + 2 * NT) * (int)sizeof(float);      // ~67.1KB
    const int smemMid = (2 * HID * NT + KC * MPAD + 2 * NT) * (int)sizeof(float);  // ~67.1KB
    cudaFuncSetAttribute(k_gemm<FIN, false, 0>, cudaFuncAttributeMaxDynamicSharedMemorySize, smem128);
    cudaFuncSetAttribute(k_mid,                 cudaFuncAttributeMaxDynamicSharedMemorySize, smemMid);
    cudaFuncSetAttribute(k_gemm<HID, true, 2>,  cudaFuncAttributeMaxDynamicSharedMemorySize, smem64);

    int gemmBlocks = (NN + MT - 1) / MT;           // 782
    int edgeBlocks = (EE + 255) / 256;             // 6250
    int aggBlocks  = (NN * 16 + 255) / 256;        // 6250

    // slot 1-3: zero + CSR start
    k_zero_all<<<(NN + 255) / 256, 256>>>(out);
    k_hist<<<edgeBlocks, 256>>>(ei);
    k_scan1<<<NCHUNK, SCAN_CHUNK>>>();
    // slot 4 (profiled): the K=128 tiled GEMM — dependency-free, so CSR chain unaffected
    k_gemm<FIN, false, 0><<<gemmBlocks, 256, smem128>>>(
        x, W1a, yP, nullptr, nullptr, nullptr, nullptr, nullptr, nullptr, nullptr);
    k_scan3f<<<(NN + 255) / 256, 256>>>();
    k_reorder<<<edgeBlocks, 256>>>(ei);

    // layer 1 + mid
    k_agg<<<aggBlocks, 256>>>(b1a);
    k_mid<<<gemmBlocks, 256, smemMid>>>(W1b, b1b, g1, be1, m1, v1, W2a);

    // layer 2
    k_agg<<<aggBlocks, 256>>>(b2a);
    k_gemm<HID, true, 2><<<gemmBlocks, 256, smem64>>>(
        aP, W2b, nullptr, b2b, g2, be2, m2, v2, batch, out);
    k_div<<<NG, HID>>>(batch, out);
}